// round 1
// baseline (speedup 1.0000x reference)
#include <cuda_runtime.h>
#include <cstdint>
#include <cstddef>

#define BB 512
#define TT 1024
#define INDIM 32
#define HH 128
#define GG 512            // 4*H
#define DLL 256
#define OUTD 32
#define M_TOT (BB*TT)     // 524288

#define KSM 112           // Whh k-rows kept in smem
#define KTL 16            // Whh k-rows kept in registers

#define LSTM_SMEM ((KSM*GG + GG) * 4)            // 231424 bytes
#define GEMM_LD 68
#define GEMM_SMEM (2 * 128 * GEMM_LD * 4)        // 69632 bytes

// -------- device scratch (static; no runtime allocation) --------
__device__ float g_xg[(size_t)M_TOT * GG];       // 1 GB: pre-gates for current layer
__device__ float g_h0[(size_t)M_TOT * HH];       // 256 MB: layer-0 hidden sequence
__device__ float g_hlast[BB * HH];
__device__ float g_WT0[HH * GG];                 // Whh0^T  [k][g]
__device__ float g_WT1[HH * GG];                 // Whh1^T  [k][g]

// -------- transpose Whh [512][128] -> WT [128][512] --------
__global__ void transpose_whh(const float* __restrict__ W, float* __restrict__ WT) {
    int idx = blockIdx.x * 256 + threadIdx.x;    // 65536 total
    if (idx < HH * GG) {
        int k = idx / GG;
        int g = idx - k * GG;
        WT[idx] = W[g * HH + k];
    }
}

// -------- tiled fp32 GEMM with bias: C[m][n] = sum_k A[m][k]*W[n][k] + ba[n] + bb[n] --------
__global__ void __launch_bounds__(256) gemm_bias_kernel(
    const float* __restrict__ A, const float* __restrict__ W,
    const float* __restrict__ ba, const float* __restrict__ bb,
    float* __restrict__ C, int M, int N, int K)
{
    extern __shared__ float sm[];
    float* sA = sm;                     // [K][GEMM_LD]
    float* sB = sm + 128 * GEMM_LD;     // [K][GEMM_LD]
    const int tid = threadIdx.x;
    const int m0 = blockIdx.x * 64;
    const int n0 = blockIdx.y * 64;
    const int kv = K >> 2;

    for (int idx = tid; idx < 64 * kv; idx += 256) {
        int m = idx / kv;
        int kq = (idx - m * kv) << 2;
        float4 v = *(const float4*)(A + (size_t)(m0 + m) * K + kq);
        sA[(kq + 0) * GEMM_LD + m] = v.x;
        sA[(kq + 1) * GEMM_LD + m] = v.y;
        sA[(kq + 2) * GEMM_LD + m] = v.z;
        sA[(kq + 3) * GEMM_LD + m] = v.w;
    }
    for (int idx = tid; idx < 64 * kv; idx += 256) {
        int n = idx / kv;
        int kq = (idx - n * kv) << 2;
        float4 v = *(const float4*)(W + (size_t)(n0 + n) * K + kq);
        sB[(kq + 0) * GEMM_LD + n] = v.x;
        sB[(kq + 1) * GEMM_LD + n] = v.y;
        sB[(kq + 2) * GEMM_LD + n] = v.z;
        sB[(kq + 3) * GEMM_LD + n] = v.w;
    }
    __syncthreads();

    const int rg = (tid >> 4) << 2;     // row group  (0..60)
    const int cg = (tid & 15) << 2;     // col group  (0..60)
    float acc[4][4] = {};

    for (int k = 0; k < K; k++) {
        float4 a = *(float4*)(sA + k * GEMM_LD + rg);
        float4 b = *(float4*)(sB + k * GEMM_LD + cg);
        acc[0][0] += a.x * b.x; acc[0][1] += a.x * b.y; acc[0][2] += a.x * b.z; acc[0][3] += a.x * b.w;
        acc[1][0] += a.y * b.x; acc[1][1] += a.y * b.y; acc[1][2] += a.y * b.z; acc[1][3] += a.y * b.w;
        acc[2][0] += a.z * b.x; acc[2][1] += a.z * b.y; acc[2][2] += a.z * b.z; acc[2][3] += a.z * b.w;
        acc[3][0] += a.w * b.x; acc[3][1] += a.w * b.y; acc[3][2] += a.w * b.z; acc[3][3] += a.w * b.w;
    }

    float bx = ba[n0 + cg + 0] + bb[n0 + cg + 0];
    float by = ba[n0 + cg + 1] + bb[n0 + cg + 1];
    float bz = ba[n0 + cg + 2] + bb[n0 + cg + 2];
    float bw = ba[n0 + cg + 3] + bb[n0 + cg + 3];
    #pragma unroll
    for (int i = 0; i < 4; i++) {
        float4 o;
        o.x = acc[i][0] + bx; o.y = acc[i][1] + by; o.z = acc[i][2] + bz; o.w = acc[i][3] + bw;
        *(float4*)(C + (size_t)(m0 + rg + i) * N + n0 + cg) = o;
    }
}

// -------- LSTM recurrence: one CTA owns 4 batch rows for all T steps --------
__device__ __forceinline__ float sigf(float x) { return 1.0f / (1.0f + __expf(-x)); }

__global__ void __launch_bounds__(256, 1) lstm_layer_kernel(
    const float* __restrict__ xg,      // [M_TOT][512] pre-gates, row = b*T + t
    const float* __restrict__ WT,      // [128][512]  Whh^T
    float* __restrict__ hout,          // [M_TOT][128] or nullptr
    float* __restrict__ hlast)         // [B][128]     or nullptr
{
    extern __shared__ float sm[];
    float* sW = sm;                    // [KSM][512]
    float* sh = sm + KSM * GG;         // [4][128]

    const int tid = threadIdx.x;
    const int j = tid & 127;
    const int u = tid >> 7;            // 0 or 1
    const int b0 = blockIdx.x * 4;
    const int r0 = b0 + 2 * u;
    const int u0 = (2 * u) * HH;

    // load Whh^T k-rows [0, KSM) into smem
    const float4* WT4 = (const float4*)WT;
    float4* sW4 = (float4*)sW;
    for (int i = tid; i < KSM * GG / 4; i += 256) sW4[i] = WT4[i];

    // tail k-rows [KSM, 128) in registers (this thread's gate column j only)
    float wt[KTL][4];
    #pragma unroll
    for (int kk = 0; kk < KTL; kk++) {
        #pragma unroll
        for (int q = 0; q < 4; q++)
            wt[kk][q] = WT[(KSM + kk) * GG + q * HH + j];
    }

    sh[tid] = 0.0f;
    sh[tid + 256] = 0.0f;
    float c0 = 0.0f, c1 = 0.0f;

    const size_t base0 = (size_t)r0 * TT * GG + j;
    const size_t base1 = (size_t)(r0 + 1) * TT * GG + j;

    // preload pre-gates for t=0
    float xc[8];
    #pragma unroll
    for (int q = 0; q < 4; q++) {
        xc[q]     = xg[base0 + q * HH];
        xc[4 + q] = xg[base1 + q * HH];
    }
    __syncthreads();

    for (int t = 0; t < TT; t++) {
        float acc[8];
        #pragma unroll
        for (int i2 = 0; i2 < 8; i2++) acc[i2] = xc[i2];

        // software-prefetch next step's pre-gates (overlaps with dot loop)
        float xn[8];
        #pragma unroll
        for (int i2 = 0; i2 < 8; i2++) xn[i2] = 0.0f;
        if (t + 1 < TT) {
            size_t o0 = base0 + (size_t)(t + 1) * GG;
            size_t o1 = base1 + (size_t)(t + 1) * GG;
            #pragma unroll
            for (int q = 0; q < 4; q++) {
                xn[q]     = xg[o0 + q * HH];
                xn[4 + q] = xg[o1 + q * HH];
            }
        }

        // gates += h @ Whh^T  (smem part)
        #pragma unroll 4
        for (int k = 0; k < KSM; k++) {
            float h0v = sh[u0 + k];
            float h1v = sh[u0 + HH + k];
            const float* w = &sW[k * GG + j];
            float wi = w[0], wf = w[HH], wg = w[2 * HH], wo = w[3 * HH];
            acc[0] += h0v * wi; acc[1] += h0v * wf; acc[2] += h0v * wg; acc[3] += h0v * wo;
            acc[4] += h1v * wi; acc[5] += h1v * wf; acc[6] += h1v * wg; acc[7] += h1v * wo;
        }
        // register-tail part
        #pragma unroll
        for (int kk = 0; kk < KTL; kk++) {
            float h0v = sh[u0 + KSM + kk];
            float h1v = sh[u0 + HH + KSM + kk];
            acc[0] += h0v * wt[kk][0]; acc[1] += h0v * wt[kk][1];
            acc[2] += h0v * wt[kk][2]; acc[3] += h0v * wt[kk][3];
            acc[4] += h1v * wt[kk][0]; acc[5] += h1v * wt[kk][1];
            acc[6] += h1v * wt[kk][2]; acc[7] += h1v * wt[kk][3];
        }

        // cell update (i, f, g, o order matches jnp.split)
        float i0 = sigf(acc[0]), f0 = sigf(acc[1]), g0 = tanhf(acc[2]), o0g = sigf(acc[3]);
        c0 = f0 * c0 + i0 * g0;
        float h0n = o0g * tanhf(c0);
        float i1 = sigf(acc[4]), f1 = sigf(acc[5]), g1 = tanhf(acc[6]), o1g = sigf(acc[7]);
        c1 = f1 * c1 + i1 * g1;
        float h1n = o1g * tanhf(c1);

        __syncthreads();   // everyone done reading old h
        sh[u0 + j] = h0n;
        sh[u0 + HH + j] = h1n;
        if (hout) {
            hout[((size_t)r0 * TT + t) * HH + j] = h0n;
            hout[((size_t)(r0 + 1) * TT + t) * HH + j] = h1n;
        }
        if (hlast && t == TT - 1) {
            hlast[r0 * HH + j] = h0n;
            hlast[(r0 + 1) * HH + j] = h1n;
        }
        __syncthreads();   // new h visible

        #pragma unroll
        for (int i2 = 0; i2 < 8; i2++) xc[i2] = xn[i2];
    }
}

// -------- MLP head: y = celu(celu(last @ W1^T + b1) @ W2^T + b2) --------
__device__ __forceinline__ float celuf(float x) { return x > 0.0f ? x : expm1f(x); }

__global__ void __launch_bounds__(256) head_kernel(
    const float* __restrict__ hlast,
    const float* __restrict__ W1, const float* __restrict__ b1,
    const float* __restrict__ W2, const float* __restrict__ b2,
    float* __restrict__ out)
{
    const int b = blockIdx.x;
    const int tid = threadIdx.x;
    __shared__ float sl[HH];
    __shared__ float sy[DLL];

    if (tid < HH) sl[tid] = hlast[b * HH + tid];
    __syncthreads();

    float s = b1[tid];
    const float* w = W1 + (size_t)tid * HH;
    #pragma unroll 8
    for (int k = 0; k < HH; k++) s += sl[k] * w[k];
    sy[tid] = celuf(s);
    __syncthreads();

    if (tid < OUTD) {
        float s2 = b2[tid];
        const float* w2 = W2 + (size_t)tid * DLL;
        #pragma unroll 8
        for (int k = 0; k < DLL; k++) s2 += sy[k] * w2[k];
        out[b * OUTD + tid] = celuf(s2);
    }
}

__global__ void zero_tail(float* __restrict__ p, int n) {
    int i = blockIdx.x * 256 + threadIdx.x;
    if (i < n) p[i] = 0.0f;
}

// -------- launch --------
extern "C" void kernel_launch(void* const* d_in, const int* in_sizes, int n_in,
                              void* d_out, int out_size)
{
    const float* x    = (const float*)d_in[0];
    const float* Wih0 = (const float*)d_in[1];
    const float* Whh0 = (const float*)d_in[2];
    const float* bih0 = (const float*)d_in[3];
    const float* bhh0 = (const float*)d_in[4];
    const float* Wih1 = (const float*)d_in[5];
    const float* Whh1 = (const float*)d_in[6];
    const float* bih1 = (const float*)d_in[7];
    const float* bhh1 = (const float*)d_in[8];
    const float* W1   = (const float*)d_in[9];
    const float* b1   = (const float*)d_in[10];
    const float* W2   = (const float*)d_in[11];
    const float* b2   = (const float*)d_in[12];
    float* out = (float*)d_out;

    float *xgp, *h0p, *hlastp, *wt0p, *wt1p;
    cudaGetSymbolAddress((void**)&xgp,   g_xg);
    cudaGetSymbolAddress((void**)&h0p,   g_h0);
    cudaGetSymbolAddress((void**)&hlastp,g_hlast);
    cudaGetSymbolAddress((void**)&wt0p,  g_WT0);
    cudaGetSymbolAddress((void**)&wt1p,  g_WT1);

    cudaFuncSetAttribute(lstm_layer_kernel, cudaFuncAttributeMaxDynamicSharedMemorySize, LSTM_SMEM);
    cudaFuncSetAttribute(gemm_bias_kernel,  cudaFuncAttributeMaxDynamicSharedMemorySize, GEMM_SMEM);

    transpose_whh<<<256, 256>>>(Whh0, wt0p);
    transpose_whh<<<256, 256>>>(Whh1, wt1p);

    // layer 0: pre-gates then recurrence
    gemm_bias_kernel<<<dim3(M_TOT / 64, GG / 64), 256, GEMM_SMEM>>>(
        x, Wih0, bih0, bhh0, xgp, M_TOT, GG, INDIM);
    lstm_layer_kernel<<<BB / 4, 256, LSTM_SMEM>>>(xgp, wt0p, h0p, nullptr);

    // layer 1: pre-gates (from h0) then recurrence
    gemm_bias_kernel<<<dim3(M_TOT / 64, GG / 64), 256, GEMM_SMEM>>>(
        h0p, Wih1, bih1, bhh1, xgp, M_TOT, GG, HH);
    lstm_layer_kernel<<<BB / 4, 256, LSTM_SMEM>>>(xgp, wt1p, nullptr, hlastp);

    // head + zero hidden_init portion of output
    head_kernel<<<BB, 256>>>(hlastp, W1, b1, W2, b2, out);
    int tail = out_size - BB * OUTD;
    if (tail > 0)
        zero_tail<<<(tail + 255) / 256, 256>>>(out + BB * OUTD, tail);
}

// round 2
// speedup vs baseline: 1.6818x; 1.6818x over previous
#include <cuda_runtime.h>
#include <cstdint>
#include <cstddef>

typedef unsigned long long ull;

#define BB 512
#define TT 1024
#define INDIM 32
#define HH 128
#define GG 512            // 4*H
#define DLL 256
#define OUTD 32
#define M_TOT (BB*TT)     // 524288

#define KSM 104           // Whh k-rows kept in smem (interleaved)
#define LSTM_SMEM ((KSM*GG + 512 + 2048) * 4)   // 223232 bytes: weights + h + exchange

#define GLD 132
#define GEMM_SMEM_MAX (2 * 128 * GLD * 4)       // 135168 bytes (K=128 case)

// -------- device scratch (static; no runtime allocation) --------
__device__ float g_xg[(size_t)M_TOT * GG];       // pre-gates for current layer
__device__ float g_h0[(size_t)M_TOT * HH];       // layer-0 hidden sequence
__device__ float g_hlast[BB * HH];
__device__ float g_WT0[HH * GG];                 // Whh0 interleaved [k][j][gate]
__device__ float g_WT1[HH * GG];

// ---------------- f32x2 helpers ----------------
__device__ __forceinline__ ull fma2(ull a, ull b, ull c) {
    ull d;
    asm("fma.rn.f32x2 %0, %1, %2, %3;" : "=l"(d) : "l"(a), "l"(b), "l"(c));
    return d;
}
__device__ __forceinline__ ull add2(ull a, ull b) {
    ull d;
    asm("add.rn.f32x2 %0, %1, %2;" : "=l"(d) : "l"(a), "l"(b));
    return d;
}
__device__ __forceinline__ ull pack2(float x, float y) {
    ull d;
    asm("mov.b64 %0, {%1, %2};" : "=l"(d) : "r"(__float_as_uint(x)), "r"(__float_as_uint(y)));
    return d;
}
__device__ __forceinline__ ull dup2(float x) {
    unsigned v = __float_as_uint(x);
    ull d;
    asm("mov.b64 %0, {%1, %1};" : "=l"(d) : "r"(v));
    return d;
}
__device__ __forceinline__ void unpack2(ull v, float& x, float& y) {
    unsigned a, b;
    asm("mov.b64 {%0, %1}, %2;" : "=r"(a), "=r"(b) : "l"(v));
    x = __uint_as_float(a);
    y = __uint_as_float(b);
}

__device__ __forceinline__ float sigf(float x)  { return __fdividef(1.0f, 1.0f + __expf(-x)); }
__device__ __forceinline__ float tanhx(float x) { return __fdividef(2.0f, 1.0f + __expf(-2.0f * x)) - 1.0f; }

// -------- interleave Whh [512][128] -> WTI [128][128][4]: WTI[k][j][q] = Whh[q*128+j][k] --------
__global__ void prep_whh(const float* __restrict__ W, float* __restrict__ WTI) {
    int idx = blockIdx.x * 256 + threadIdx.x;    // 65536 total
    if (idx < HH * GG) {
        int k = idx >> 9;
        int rem = idx & 511;
        int jj = rem >> 2;
        int q = rem & 3;
        WTI[idx] = W[(q * HH + jj) * HH + k];
    }
}

// -------- 128x128-tile fp32 GEMM (FFMA2): C[m][n] = sum_k A[m][k]*W[n][k] + ba[n] + bb[n] --------
__global__ void __launch_bounds__(256) gemm2_kernel(
    const float* __restrict__ A, const float* __restrict__ W,
    const float* __restrict__ ba, const float* __restrict__ bb,
    float* __restrict__ C, int M, int N, int K)
{
    extern __shared__ float sm[];
    float* sA = sm;                 // [K][GLD]
    float* sB = sm + K * GLD;       // [K][GLD]
    const int tid = threadIdx.x;
    const int m0 = blockIdx.x * 128;
    const int n0 = blockIdx.y * 128;
    const int kv = K >> 2;

    for (int idx = tid; idx < 128 * kv; idx += 256) {
        int m = idx / kv;
        int kq = (idx - m * kv) << 2;
        float4 v = *(const float4*)(A + (size_t)(m0 + m) * K + kq);
        sA[(kq + 0) * GLD + m] = v.x;
        sA[(kq + 1) * GLD + m] = v.y;
        sA[(kq + 2) * GLD + m] = v.z;
        sA[(kq + 3) * GLD + m] = v.w;
    }
    for (int idx = tid; idx < 128 * kv; idx += 256) {
        int n = idx / kv;
        int kq = (idx - n * kv) << 2;
        float4 v = *(const float4*)(W + (size_t)(n0 + n) * K + kq);
        sB[(kq + 0) * GLD + n] = v.x;
        sB[(kq + 1) * GLD + n] = v.y;
        sB[(kq + 2) * GLD + n] = v.z;
        sB[(kq + 3) * GLD + n] = v.w;
    }
    __syncthreads();

    const int ty = tid >> 4;          // 0..15
    const int tx = tid & 15;          // 0..15
    const int ra = ty * 4;            // rows ra..ra+3 and rb..rb+3
    const int rb = 64 + ty * 4;
    const int c0 = tx * 4;            // cols c0..c0+3 and c1..c1+3
    const int c1 = 64 + tx * 4;

    ull acc[8][4];
    #pragma unroll
    for (int i = 0; i < 8; i++)
        #pragma unroll
        for (int p = 0; p < 4; p++) acc[i][p] = 0ULL;

    #pragma unroll 4
    for (int k = 0; k < K; k++) {
        float4 a0 = *(const float4*)(sA + k * GLD + ra);
        float4 a1 = *(const float4*)(sA + k * GLD + rb);
        float4 b0 = *(const float4*)(sB + k * GLD + c0);
        float4 b1 = *(const float4*)(sB + k * GLD + c1);
        ull bp0 = pack2(b0.x, b0.y), bp1 = pack2(b0.z, b0.w);
        ull bp2 = pack2(b1.x, b1.y), bp3 = pack2(b1.z, b1.w);
        float av[8] = {a0.x, a0.y, a0.z, a0.w, a1.x, a1.y, a1.z, a1.w};
        #pragma unroll
        for (int i = 0; i < 8; i++) {
            ull d = dup2(av[i]);
            acc[i][0] = fma2(d, bp0, acc[i][0]);
            acc[i][1] = fma2(d, bp1, acc[i][1]);
            acc[i][2] = fma2(d, bp2, acc[i][2]);
            acc[i][3] = fma2(d, bp3, acc[i][3]);
        }
    }

    ull bias0 = pack2(ba[n0 + c0 + 0] + bb[n0 + c0 + 0], ba[n0 + c0 + 1] + bb[n0 + c0 + 1]);
    ull bias1 = pack2(ba[n0 + c0 + 2] + bb[n0 + c0 + 2], ba[n0 + c0 + 3] + bb[n0 + c0 + 3]);
    ull bias2 = pack2(ba[n0 + c1 + 0] + bb[n0 + c1 + 0], ba[n0 + c1 + 1] + bb[n0 + c1 + 1]);
    ull bias3 = pack2(ba[n0 + c1 + 2] + bb[n0 + c1 + 2], ba[n0 + c1 + 3] + bb[n0 + c1 + 3]);

    #pragma unroll
    for (int i = 0; i < 8; i++) {
        int row = m0 + (i < 4 ? ra + i : rb + i - 4);
        ull* p0 = (ull*)(C + (size_t)row * N + n0 + c0);
        p0[0] = add2(acc[i][0], bias0);
        p0[1] = add2(acc[i][1], bias1);
        ull* p1 = (ull*)(C + (size_t)row * N + n0 + c1);
        p1[0] = add2(acc[i][2], bias2);
        p1[1] = add2(acc[i][3], bias3);
    }
}

// -------- LSTM recurrence: 4 batch rows per CTA, k-split across thread halves, FFMA2 --------
#define RSTEP(C, KD) { \
    ull w01 = sw2[(size_t)(k + KD) * 256 + jj2]; \
    ull w23 = sw2[(size_t)(k + KD) * 256 + jj2 + 1]; \
    ull d0 = dup2(h0.C), d1 = dup2(h1.C), d2 = dup2(h2.C), d3 = dup2(h3.C); \
    acc00 = fma2(d0, w01, acc00); acc01 = fma2(d0, w23, acc01); \
    acc10 = fma2(d1, w01, acc10); acc11 = fma2(d1, w23, acc11); \
    acc20 = fma2(d2, w01, acc20); acc21 = fma2(d2, w23, acc21); \
    acc30 = fma2(d3, w01, acc30); acc31 = fma2(d3, w23, acc31); }

#define TSTEP(C, QI, KD) { \
    ull w01 = wtp[(QI * 4 + KD) * 2]; \
    ull w23 = wtp[(QI * 4 + KD) * 2 + 1]; \
    ull d0 = dup2(h0.C), d1 = dup2(h1.C), d2 = dup2(h2.C), d3 = dup2(h3.C); \
    acc00 = fma2(d0, w01, acc00); acc01 = fma2(d0, w23, acc01); \
    acc10 = fma2(d1, w01, acc10); acc11 = fma2(d1, w23, acc11); \
    acc20 = fma2(d2, w01, acc20); acc21 = fma2(d2, w23, acc21); \
    acc30 = fma2(d3, w01, acc31 = acc31), acc30 = fma2(d3, w01, acc30); acc31 = fma2(d3, w23, acc31); }

// (note: TSTEP rewritten cleanly below via TSTEP2)
#undef TSTEP
#define TSTEP(C, QI, KD) { \
    ull w01 = wtp[(QI * 4 + KD) * 2]; \
    ull w23 = wtp[(QI * 4 + KD) * 2 + 1]; \
    ull d0 = dup2(h0.C), d1 = dup2(h1.C), d2 = dup2(h2.C), d3 = dup2(h3.C); \
    acc00 = fma2(d0, w01, acc00); acc01 = fma2(d0, w23, acc01); \
    acc10 = fma2(d1, w01, acc10); acc11 = fma2(d1, w23, acc11); \
    acc20 = fma2(d2, w01, acc20); acc21 = fma2(d2, w23, acc21); \
    acc30 = fma2(d3, w01, acc30); acc31 = fma2(d3, w23, acc31); }

__global__ void __launch_bounds__(256, 1) lstm_layer_kernel(
    const float* __restrict__ xg,      // [M_TOT][512] pre-gates, row = b*T + t
    const float* __restrict__ WTI,     // [128][128][4] interleaved Whh
    float* __restrict__ hout,          // [M_TOT][128] or nullptr
    float* __restrict__ hlast)         // [B][128]     or nullptr
{
    extern __shared__ float sm[];
    float* sW = sm;                          // [104][512] interleaved
    float* sh = sm + KSM * GG;               // [4][128]
    ull*   sx = (ull*)(sm + KSM * GG + 512); // [4][2][128] exchange

    const int tid = threadIdx.x;
    const int j = tid & 127;
    const int u = tid >> 7;              // k-half selector
    const int b0 = blockIdx.x * 4;

    const ull* sw2 = (const ull*)sW;
    const int jj2 = j * 2;

    // load weights k in [0, KSM) into smem (interleaved, float4 copy)
    {
        const float4* g4 = (const float4*)WTI;
        float4* s4 = (float4*)sW;
        for (int i = tid; i < KSM * 128; i += 256) s4[i] = g4[i];
    }
    // tail weights k in [104,128) split per half, held in registers as f32x2 pairs
    ull wtp[24];
    {
        int kt = KSM + u * 12;
        #pragma unroll
        for (int i = 0; i < 12; i++) {
            const ull* p = (const ull*)(WTI + (size_t)(kt + i) * GG + j * 4);
            wtp[i * 2] = p[0];
            wtp[i * 2 + 1] = p[1];
        }
    }
    sh[tid] = 0.0f;
    sh[tid + 256] = 0.0f;

    // logical row mapping: rows 0,1 = own (physical 2u, 2u+1); rows 2,3 = other half's
    const int hofs0 = (2 * u) * HH;
    const int hofs1 = hofs0 + HH;
    const int hofs2 = (2 * (1 - u)) * HH;
    const int hofs3 = hofs2 + HH;

    const size_t xbaseA = ((size_t)(b0 + 2 * u)) * TT * GG + j;
    const size_t xbaseB = xbaseA + (size_t)TT * GG;
    float* houtA = hout ? hout + ((size_t)(b0 + 2 * u)) * TT * HH + j : (float*)0;
    float* houtB = hout ? houtA + (size_t)TT * HH : (float*)0;

    ull xc0 = pack2(xg[xbaseA], xg[xbaseA + 128]);
    ull xc1 = pack2(xg[xbaseA + 256], xg[xbaseA + 384]);
    ull xc2 = pack2(xg[xbaseB], xg[xbaseB + 128]);
    ull xc3 = pack2(xg[xbaseB + 256], xg[xbaseB + 384]);

    float ca = 0.0f, cb = 0.0f, ha = 0.0f, hb = 0.0f;
    const int klo = u * 52;
    const int kt0 = KSM + u * 12;
    __syncthreads();

    for (int t = 0; t < TT; t++) {
        // own rows start with their pre-gates; other rows' partials start at 0
        ull acc00 = xc0, acc01 = xc1, acc10 = xc2, acc11 = xc3;
        ull acc20 = 0, acc21 = 0, acc30 = 0, acc31 = 0;

        // prefetch next step's pre-gates (consumed after the k-loop)
        float xn0 = 0, xn1 = 0, xn2 = 0, xn3 = 0, xn4 = 0, xn5 = 0, xn6 = 0, xn7 = 0;
        if (t + 1 < TT) {
            size_t oA = xbaseA + (size_t)(t + 1) * GG;
            size_t oB = xbaseB + (size_t)(t + 1) * GG;
            xn0 = xg[oA]; xn1 = xg[oA + 128]; xn2 = xg[oA + 256]; xn3 = xg[oA + 384];
            xn4 = xg[oB]; xn5 = xg[oB + 128]; xn6 = xg[oB + 256]; xn7 = xg[oB + 384];
        }

        // smem k-half: 52 k-rows
        #pragma unroll 2
        for (int qi = 0; qi < 13; qi++) {
            int k = klo + qi * 4;
            float4 h0 = *(const float4*)(sh + hofs0 + k);
            float4 h1 = *(const float4*)(sh + hofs1 + k);
            float4 h2 = *(const float4*)(sh + hofs2 + k);
            float4 h3 = *(const float4*)(sh + hofs3 + k);
            RSTEP(x, 0) RSTEP(y, 1) RSTEP(z, 2) RSTEP(w, 3)
        }
        // register tail: 12 k-rows
        {
            int k = kt0;
            {
                float4 h0 = *(const float4*)(sh + hofs0 + k);
                float4 h1 = *(const float4*)(sh + hofs1 + k);
                float4 h2 = *(const float4*)(sh + hofs2 + k);
                float4 h3 = *(const float4*)(sh + hofs3 + k);
                TSTEP(x, 0, 0) TSTEP(y, 0, 1) TSTEP(z, 0, 2) TSTEP(w, 0, 3)
            }
            k += 4;
            {
                float4 h0 = *(const float4*)(sh + hofs0 + k);
                float4 h1 = *(const float4*)(sh + hofs1 + k);
                float4 h2 = *(const float4*)(sh + hofs2 + k);
                float4 h3 = *(const float4*)(sh + hofs3 + k);
                TSTEP(x, 1, 0) TSTEP(y, 1, 1) TSTEP(z, 1, 2) TSTEP(w, 1, 3)
            }
            k += 4;
            {
                float4 h0 = *(const float4*)(sh + hofs0 + k);
                float4 h1 = *(const float4*)(sh + hofs1 + k);
                float4 h2 = *(const float4*)(sh + hofs2 + k);
                float4 h3 = *(const float4*)(sh + hofs3 + k);
                TSTEP(x, 2, 0) TSTEP(y, 2, 1) TSTEP(z, 2, 2) TSTEP(w, 2, 3)
            }
        }

        // exchange partials for the other half's rows
        sx[u * 128 + j]       = acc20;
        sx[u * 128 + j + 256] = acc21;
        sx[u * 128 + j + 512] = acc30;
        sx[u * 128 + j + 768] = acc31;
        __syncthreads();
        {
            int pj = (1 - u) * 128 + j;
            ull t0 = add2(acc00, sx[pj]);
            ull t1 = add2(acc01, sx[pj + 256]);
            ull t2 = add2(acc10, sx[pj + 512]);
            ull t3 = add2(acc11, sx[pj + 768]);

            float gi, gf, gg, go;
            unpack2(t0, gi, gf); unpack2(t1, gg, go);
            float ii = sigf(gi), ff = sigf(gf), g = tanhx(gg), oo = sigf(go);
            ca = ff * ca + ii * g;
            ha = oo * tanhx(ca);
            unpack2(t2, gi, gf); unpack2(t3, gg, go);
            ii = sigf(gi); ff = sigf(gf); g = tanhx(gg); oo = sigf(go);
            cb = ff * cb + ii * g;
            hb = oo * tanhx(cb);

            sh[hofs0 + j] = ha;
            sh[hofs1 + j] = hb;
            if (hout) {
                houtA[(size_t)t * HH] = ha;
                houtB[(size_t)t * HH] = hb;
            }
        }
        xc0 = pack2(xn0, xn1); xc1 = pack2(xn2, xn3);
        xc2 = pack2(xn4, xn5); xc3 = pack2(xn6, xn7);
        __syncthreads();
    }

    if (hlast) {
        hlast[(b0 + 2 * u) * HH + j] = ha;
        hlast[(b0 + 2 * u + 1) * HH + j] = hb;
    }
}

// -------- MLP head: y = celu(celu(last @ W1^T + b1) @ W2^T + b2) --------
__device__ __forceinline__ float celuf(float x) { return x > 0.0f ? x : expm1f(x); }

__global__ void __launch_bounds__(256) head_kernel(
    const float* __restrict__ hlast,
    const float* __restrict__ W1, const float* __restrict__ b1,
    const float* __restrict__ W2, const float* __restrict__ b2,
    float* __restrict__ out)
{
    const int b = blockIdx.x;
    const int tid = threadIdx.x;
    __shared__ float sl[HH];
    __shared__ float sy[DLL];

    if (tid < HH) sl[tid] = hlast[b * HH + tid];
    __syncthreads();

    float s = b1[tid];
    const float* w = W1 + (size_t)tid * HH;
    #pragma unroll 8
    for (int k = 0; k < HH; k++) s += sl[k] * w[k];
    sy[tid] = celuf(s);
    __syncthreads();

    if (tid < OUTD) {
        float s2 = b2[tid];
        const float* w2 = W2 + (size_t)tid * DLL;
        #pragma unroll 8
        for (int k = 0; k < DLL; k++) s2 += sy[k] * w2[k];
        out[b * OUTD + tid] = celuf(s2);
    }
}

__global__ void zero_tail(float* __restrict__ p, int n) {
    int i = blockIdx.x * 256 + threadIdx.x;
    if (i < n) p[i] = 0.0f;
}

// -------- launch --------
extern "C" void kernel_launch(void* const* d_in, const int* in_sizes, int n_in,
                              void* d_out, int out_size)
{
    const float* x    = (const float*)d_in[0];
    const float* Wih0 = (const float*)d_in[1];
    const float* Whh0 = (const float*)d_in[2];
    const float* bih0 = (const float*)d_in[3];
    const float* bhh0 = (const float*)d_in[4];
    const float* Wih1 = (const float*)d_in[5];
    const float* Whh1 = (const float*)d_in[6];
    const float* bih1 = (const float*)d_in[7];
    const float* bhh1 = (const float*)d_in[8];
    const float* W1   = (const float*)d_in[9];
    const float* b1   = (const float*)d_in[10];
    const float* W2   = (const float*)d_in[11];
    const float* b2   = (const float*)d_in[12];
    float* out = (float*)d_out;

    float *xgp, *h0p, *hlastp, *wt0p, *wt1p;
    cudaGetSymbolAddress((void**)&xgp,    g_xg);
    cudaGetSymbolAddress((void**)&h0p,    g_h0);
    cudaGetSymbolAddress((void**)&hlastp, g_hlast);
    cudaGetSymbolAddress((void**)&wt0p,   g_WT0);
    cudaGetSymbolAddress((void**)&wt1p,   g_WT1);

    cudaFuncSetAttribute(lstm_layer_kernel, cudaFuncAttributeMaxDynamicSharedMemorySize, LSTM_SMEM);
    cudaFuncSetAttribute(gemm2_kernel,      cudaFuncAttributeMaxDynamicSharedMemorySize, GEMM_SMEM_MAX);

    prep_whh<<<256, 256>>>(Whh0, wt0p);
    prep_whh<<<256, 256>>>(Whh1, wt1p);

    // layer 0: pre-gates (K=32) then recurrence
    gemm2_kernel<<<dim3(M_TOT / 128, GG / 128), 256, 2 * INDIM * GLD * 4>>>(
        x, Wih0, bih0, bhh0, xgp, M_TOT, GG, INDIM);
    lstm_layer_kernel<<<BB / 4, 256, LSTM_SMEM>>>(xgp, wt0p, h0p, nullptr);

    // layer 1: pre-gates (K=128) then recurrence
    gemm2_kernel<<<dim3(M_TOT / 128, GG / 128), 256, 2 * HH * GLD * 4>>>(
        h0p, Wih1, bih1, bhh1, xgp, M_TOT, GG, HH);
    lstm_layer_kernel<<<BB / 4, 256, LSTM_SMEM>>>(xgp, wt1p, nullptr, hlastp);

    // head + zero hidden_init portion of output
    head_kernel<<<BB, 256>>>(hlastp, W1, b1, W2, b2, out);
    int tail = out_size - BB * OUTD;
    if (tail > 0)
        zero_tail<<<(tail + 255) / 256, 256>>>(out + BB * OUTD, tail);
}